// round 1
// baseline (speedup 1.0000x reference)
#include <cuda_runtime.h>

#define NT   256
#define ROWS 16
#define IT   4

__device__ double g_sum;
__device__ double g_adj;

__global__ void init_k() { g_sum = 0.0; g_adj = 0.0; }

__device__ __forceinline__ float sqrt_approx(float x) {
    float y; asm("sqrt.approx.f32 %0, %1;" : "=f"(y) : "f"(x)); return y;
}

extern __shared__ float4 s_pts[];  // [0,N): preds {x,y,z,|p|^2}; [N,2N): targets

__global__ void __launch_bounds__(NT, 2)
loss_kernel(const float* __restrict__ preds,
            const float* __restrict__ targets,
            const float* __restrict__ adj,
            int N)
{
    const int b    = blockIdx.y;
    const int row0 = blockIdx.x * ROWS;
    float4* sp = s_pts;
    float4* st = s_pts + N;

    // Stage points + squared norms into SMEM (tiny: 24KB reads, L2-resident)
    {
        const float* pb = preds   + (size_t)b * N * 3;
        const float* tb = targets + (size_t)b * N * 3;
        for (int k = threadIdx.x; k < N; k += NT) {
            float x = pb[3*k], y = pb[3*k+1], z = pb[3*k+2];
            sp[k] = make_float4(x, y, z, fmaf(x, x, fmaf(y, y, z*z)));
            float u = tb[3*k], v = tb[3*k+1], w = tb[3*k+2];
            st[k] = make_float4(u, v, w, fmaf(u, u, fmaf(v, v, w*w)));
        }
    }
    __syncthreads();

    float acc = 0.f, accA = 0.f;
    const int N4 = N >> 2;
    const float* adjB = adj + (size_t)b * N * N;

    for (int ig = 0; ig < ROWS; ig += IT) {
        // Register-block IT rows: amortize j-point LDS across 4 rows
        float4 P[IT], T[IT];
        #pragma unroll
        for (int r = 0; r < IT; r++) { P[r] = sp[row0 + ig + r]; T[r] = st[row0 + ig + r]; }

        const float4* adjRow = (const float4*)(adjB + (size_t)(row0 + ig) * N);

        for (int jv = threadIdx.x; jv < N4; jv += NT) {
            float4 pj[4], tj[4];
            #pragma unroll
            for (int q = 0; q < 4; q++) { pj[q] = sp[4*jv + q]; tj[q] = st[4*jv + q]; }

            #pragma unroll
            for (int r = 0; r < IT; r++) {
                float4 a = adjRow[(size_t)r * N4 + jv];
                float av[4] = {a.x, a.y, a.z, a.w};
                #pragma unroll
                for (int q = 0; q < 4; q++) {
                    // squared distances via norm form
                    float dotp = fmaf(P[r].x, pj[q].x, fmaf(P[r].y, pj[q].y, P[r].z * pj[q].z));
                    float sqp  = fmaf(dotp, -2.f, P[r].w + pj[q].w);
                    float dott = fmaf(T[r].x, tj[q].x, fmaf(T[r].y, tj[q].y, T[r].z * tj[q].z));
                    float sqt  = fmaf(dott, -2.f, T[r].w + tj[q].w);
                    // (sqrt(a)-sqrt(b))^2 = a + b - 2*sqrt(a*b)  -> one MUFU per element
                    float rt = sqrt_approx(fmaxf(sqp * sqt, 0.f));
                    float d2 = fmaf(-2.f, rt, sqp + sqt);
                    // adj in {0,1}: ((dp-dt)*adj)^2 == d2*adj
                    acc  = fmaf(d2, av[q], acc);
                    accA += av[q];
                }
            }
        }
    }

    // warp reduce
    #pragma unroll
    for (int off = 16; off > 0; off >>= 1) {
        acc  += __shfl_down_sync(0xffffffffu, acc,  off);
        accA += __shfl_down_sync(0xffffffffu, accA, off);
    }
    __shared__ float2 wsum[NT / 32];
    int wid = threadIdx.x >> 5, lane = threadIdx.x & 31;
    if (lane == 0) wsum[wid] = make_float2(acc, accA);
    __syncthreads();
    if (wid == 0) {
        float2 v = (lane < NT / 32) ? wsum[lane] : make_float2(0.f, 0.f);
        #pragma unroll
        for (int off = 4; off > 0; off >>= 1) {
            v.x += __shfl_down_sync(0xffffffffu, v.x, off);
            v.y += __shfl_down_sync(0xffffffffu, v.y, off);
        }
        if (lane == 0) {
            atomicAdd(&g_sum, (double)v.x);
            atomicAdd(&g_adj, (double)v.y);
        }
    }
}

__global__ void final_k(float* out) { out[0] = (float)(g_sum / g_adj); }

extern "C" void kernel_launch(void* const* d_in, const int* in_sizes, int n_in,
                              void* d_out, int out_size)
{
    const float* preds   = (const float*)d_in[0];
    const float* targets = (const float*)d_in[1];
    const float* adj     = (const float*)d_in[2];

    long long psz   = in_sizes[0];          // B*N*3
    long long adjsz = in_sizes[2];          // B*N*N
    int N = (int)(3LL * adjsz / psz);       // 2048
    int B = (int)(psz / (3LL * N));         // 8

    size_t smem = (size_t)2 * N * sizeof(float4);  // 64KB
    cudaFuncSetAttribute(loss_kernel, cudaFuncAttributeMaxDynamicSharedMemorySize, (int)smem);

    init_k<<<1, 1>>>();
    dim3 grid(N / ROWS, B);
    loss_kernel<<<grid, NT, smem>>>(preds, targets, adj, N);
    final_k<<<1, 1>>>((float*)d_out);
}